// round 1
// baseline (speedup 1.0000x reference)
#include <cuda_runtime.h>
#include <math.h>

#define HH 512
#define WW 512
#define NC 12
#define NPIX (NC*HH*WW)
#define NSIG 6
#define MAXK 155
#define MAXP 77
#define RT 16   // vertical register tile (output rows per thread)

__device__ float  g_diff[NPIX];
__device__ float  g_U[NPIX];     // row conv with E (gaussian)
__device__ float  g_V[NPIX];     // row conv with h
__device__ float  g_S[NPIX];     // row box sum
__device__ float2 g_coef[NSIG][MAXK + 5];  // (E, h)
__device__ float  g_cc[NSIG];
__device__ double g_acc[NSIG];

__constant__ int    d_k[NSIG]   = {5, 11, 21, 39, 77, 155};
__constant__ double d_sig[NSIG] = {0.6, 1.2, 2.4, 4.8, 9.6, 19.2};
__constant__ float  d_w[NSIG]   = {600.0f, 500.0f, 400.0f, 20.0f, 10.0f, 10.0f};

#define DPI 3.14159265358979323846

// ---------------------------------------------------------------------------
// Init: compute separable coefficients + mean-subtraction constant, zero accums
// ---------------------------------------------------------------------------
__global__ void init_kernel() {
    int s = blockIdx.x;
    int k = d_k[s];
    double sig = d_sig[s];
    double ss = sig * sig;
    int t = threadIdx.x;
    if (t == 0) g_acc[s] = 0.0;
    if (t < k) {
        double x = (double)t - (double)(k - 1) * 0.5;
        double e = exp(-(x * x) / (2.0 * ss));
        double h = (x * x - ss) * e / (2.0 * DPI * ss * ss);
        g_coef[s][t] = make_float2((float)e, (float)h);
    }
    __syncthreads();
    if (t == 0) {
        double sg = 0.0, sh = 0.0;
        for (int i = 0; i < k; i++) {
            sg += (double)g_coef[s][i].x;
            sh += (double)g_coef[s][i].y;
        }
        g_cc[s] = (float)(2.0 * sg * sh / ((double)k * (double)k));
    }
}

// ---------------------------------------------------------------------------
// Pass 0: d = input - target (vectorized)
// ---------------------------------------------------------------------------
__global__ void diff_kernel(const float* __restrict__ a, const float* __restrict__ b) {
    int i = blockIdx.x * blockDim.x + threadIdx.x;
    if (i < NPIX / 4) {
        float4 x = reinterpret_cast<const float4*>(a)[i];
        float4 y = reinterpret_cast<const float4*>(b)[i];
        float4 d;
        d.x = x.x - y.x; d.y = x.y - y.y; d.z = x.z - y.z; d.w = x.w - y.w;
        reinterpret_cast<float4*>(g_diff)[i] = d;
    }
}

__device__ __forceinline__ int reflect_idx(int t, int n) {
    return t < 0 ? -t : (t >= n ? 2 * n - 2 - t : t);
}

// ---------------------------------------------------------------------------
// Pass 1: horizontal convs (E, h, box) on reflect-padded rows.
// One block per image row; 256 threads; 2 outputs/thread.
// ---------------------------------------------------------------------------
__global__ void hpass_kernel(int s, int k, int p) {
    __shared__ float  srow[WW + 2 * MAXP];
    __shared__ float2 scoef[MAXK];
    int r = blockIdx.x;                 // 0 .. NC*HH-1
    const float* drow = g_diff + (size_t)r * WW;
    int tid = threadIdx.x;
    int wpad = WW + 2 * p;
    for (int idx = tid; idx < wpad; idx += 256) {
        int jj = reflect_idx(idx - p, WW);
        srow[idx] = drow[jj];
    }
    for (int idx = tid; idx < k; idx += 256) scoef[idx] = g_coef[s][idx];
    __syncthreads();

    float aE0 = 0.f, aH0 = 0.f, aS0 = 0.f;
    float aE1 = 0.f, aH1 = 0.f, aS1 = 0.f;
    int j0 = tid, j1 = tid + 256;
    for (int d = 0; d < k; ++d) {
        float2 c = scoef[d];
        float v0 = srow[j0 + d];
        float v1 = srow[j1 + d];
        aE0 = fmaf(c.x, v0, aE0); aH0 = fmaf(c.y, v0, aH0); aS0 += v0;
        aE1 = fmaf(c.x, v1, aE1); aH1 = fmaf(c.y, v1, aH1); aS1 += v1;
    }
    size_t o = (size_t)r * WW;
    g_U[o + j0] = aE0; g_V[o + j0] = aH0; g_S[o + j0] = aS0;
    g_U[o + j1] = aE1; g_V[o + j1] = aH1; g_S[o + j1] = aS1;
}

// ---------------------------------------------------------------------------
// Pass 2: vertical convs + combine + squared-sum reduction.
// result = conv_col(U, h) + conv_col(V, E) - c * conv_col(S, 1)
// Thread: one column, RT consecutive output rows (register tile).
// ---------------------------------------------------------------------------
__global__ void vpass_kernel(int s, int k, int p) {
    __shared__ float2 scoef[MAXK];
    __shared__ float  sred[4];
    int tid = threadIdx.x;  // 128
    for (int i = tid; i < k; i += 128) scoef[i] = g_coef[s][i];
    __syncthreads();

    int j   = blockIdx.x * 128 + tid;
    int i0  = blockIdx.y * RT;
    int img = blockIdx.z;
    size_t ibase = (size_t)img * HH * WW;
    const float* Up = g_U + ibase;
    const float* Vp = g_V + ibase;
    const float* Sp = g_S + ibase;
    float cc = g_cc[s];

    float A[RT], Sa[RT];
#pragma unroll
    for (int r = 0; r < RT; r++) { A[r] = 0.f; Sa[r] = 0.f; }

    if (k >= RT) {
        // prologue: t in [0, RT-2], outputs rr <= t active
        for (int t = 0; t < RT - 1; ++t) {
            int row = reflect_idx(i0 - p + t, HH);
            int off = row * WW + j;
            float u = Up[off], v = Vp[off], sv = Sp[off];
#pragma unroll
            for (int rr = 0; rr < RT; ++rr) {
                if (rr <= t) {
                    float2 c = scoef[t - rr];
                    A[rr]  = fmaf(c.y, u, fmaf(c.x, v, A[rr]));
                    Sa[rr] += sv;
                }
            }
        }
        // main: all RT outputs active, no predicates
        for (int t = RT - 1; t < k; ++t) {
            int row = reflect_idx(i0 - p + t, HH);
            int off = row * WW + j;
            float u = Up[off], v = Vp[off], sv = Sp[off];
#pragma unroll
            for (int rr = 0; rr < RT; ++rr) {
                float2 c = scoef[t - rr];
                A[rr]  = fmaf(c.y, u, A[rr]);
                A[rr]  = fmaf(c.x, v, A[rr]);
                Sa[rr] += sv;
            }
        }
        // epilogue: t in [k, k+RT-2], outputs rr >= t-k+1 active
        for (int t = k; t < k + RT - 1; ++t) {
            int row = reflect_idx(i0 - p + t, HH);
            int off = row * WW + j;
            float u = Up[off], v = Vp[off], sv = Sp[off];
#pragma unroll
            for (int rr = 0; rr < RT; ++rr) {
                if (rr >= t - k + 1) {
                    float2 c = scoef[t - rr];
                    A[rr]  = fmaf(c.y, u, fmaf(c.x, v, A[rr]));
                    Sa[rr] += sv;
                }
            }
        }
    } else {
        // small kernels (k < RT): fully predicated
        for (int t = 0; t < k + RT - 1; ++t) {
            int row = reflect_idx(i0 - p + t, HH);
            int off = row * WW + j;
            float u = Up[off], v = Vp[off], sv = Sp[off];
#pragma unroll
            for (int rr = 0; rr < RT; ++rr) {
                int di = t - rr;
                if (di >= 0 && di < k) {
                    float2 c = scoef[di];
                    A[rr]  = fmaf(c.y, u, fmaf(c.x, v, A[rr]));
                    Sa[rr] += sv;
                }
            }
        }
    }

    float sq = 0.f;
#pragma unroll
    for (int rr = 0; rr < RT; ++rr) {
        float val = fmaf(-cc, Sa[rr], A[rr]);
        sq = fmaf(val, val, sq);
    }
    // block reduction (128 threads)
#pragma unroll
    for (int o = 16; o > 0; o >>= 1) sq += __shfl_xor_sync(0xffffffffu, sq, o);
    if ((tid & 31) == 0) sred[tid >> 5] = sq;
    __syncthreads();
    if (tid == 0) {
        float tot = sred[0] + sred[1] + sred[2] + sred[3];
        atomicAdd(&g_acc[s], (double)tot);
    }
}

// ---------------------------------------------------------------------------
// Finalize: weighted sum / NPIX
// ---------------------------------------------------------------------------
__global__ void fin_kernel(float* out) {
    double L = 0.0;
    for (int s = 0; s < NSIG; s++) L += (double)d_w[s] * g_acc[s];
    out[0] = (float)(L / (double)NPIX);
}

// ---------------------------------------------------------------------------
extern "C" void kernel_launch(void* const* d_in, const int* in_sizes, int n_in,
                              void* d_out, int out_size) {
    const float* input  = (const float*)d_in[0];
    const float* target = (const float*)d_in[1];

    init_kernel<<<NSIG, 160>>>();
    diff_kernel<<<(NPIX / 4 + 255) / 256, 256>>>(input, target);

    static const int ks[NSIG] = {5, 11, 21, 39, 77, 155};
    for (int s = 0; s < NSIG; s++) {
        int k = ks[s];
        int p = k / 2;
        hpass_kernel<<<NC * HH, 256>>>(s, k, p);
        dim3 g2(WW / 128, HH / RT, NC);
        vpass_kernel<<<g2, 128>>>(s, k, p);
    }
    fin_kernel<<<1, 1>>>((float*)d_out);
}

// round 2
// speedup vs baseline: 1.8800x; 1.8800x over previous
#include <cuda_runtime.h>
#include <math.h>

#define HH 512
#define WW 512
#define W2C 256
#define NC 12
#define NPIX (NC*HH*WW)
#define NSIG 6
#define MAXK 155
#define DPI 3.14159265358979323846

typedef unsigned long long u64;

__device__ float g_diff[NPIX];
__device__ float g_U[NPIX];
__device__ float g_V[NPIX];
__device__ float g_S[NPIX];
__device__ u64   g_E2[NSIG][MAXK];
__device__ u64   g_H2[NSIG][MAXK];
__device__ float g_cc[NSIG];
__device__ double g_acc[NSIG];

__constant__ int    c_k[NSIG]   = {5, 11, 21, 39, 77, 155};
__constant__ double c_sig[NSIG] = {0.6, 1.2, 2.4, 4.8, 9.6, 19.2};
__constant__ float  c_w[NSIG]   = {600.f, 500.f, 400.f, 20.f, 10.f, 10.f};

__device__ __forceinline__ u64 pk2(float lo, float hi) {
    u64 r; asm("mov.b64 %0,{%1,%2};" : "=l"(r) : "f"(lo), "f"(hi)); return r;
}
__device__ __forceinline__ void un2(u64 v, float& lo, float& hi) {
    asm("mov.b64 {%0,%1},%2;" : "=f"(lo), "=f"(hi) : "l"(v));
}
__device__ __forceinline__ u64 fma2(u64 a, u64 b, u64 c) {
    u64 d; asm("fma.rn.f32x2 %0,%1,%2,%3;" : "=l"(d) : "l"(a), "l"(b), "l"(c)); return d;
}

// ---------------------------------------------------------------------------
__global__ void init_kernel() {
    int s = blockIdx.x;
    int k = c_k[s];
    double ss = c_sig[s] * c_sig[s];
    int t = threadIdx.x;
    if (t == 0) g_acc[s] = 0.0;
    if (t < k) {
        double x = (double)t - (double)(k - 1) * 0.5;
        double e = exp(-(x * x) / (2.0 * ss));
        double h = (x * x - ss) * e / (2.0 * DPI * ss * ss);
        g_E2[s][t] = pk2((float)e, (float)e);
        g_H2[s][t] = pk2((float)h, (float)h);
    }
    __syncthreads();
    if (t == 0) {
        double sg = 0.0, sh = 0.0;
        for (int i = 0; i < k; i++) {
            float e, e1, h, h1;
            un2(g_E2[s][i], e, e1);
            un2(g_H2[s][i], h, h1);
            sg += (double)e; sh += (double)h;
        }
        g_cc[s] = (float)(2.0 * sg * sh / ((double)k * (double)k));
    }
}

// ---------------------------------------------------------------------------
__global__ void diff_kernel(const float* __restrict__ a, const float* __restrict__ b) {
    int i = blockIdx.x * blockDim.x + threadIdx.x;
    if (i < NPIX / 4) {
        float4 x = reinterpret_cast<const float4*>(a)[i];
        float4 y = reinterpret_cast<const float4*>(b)[i];
        float4 d;
        d.x = x.x - y.x; d.y = x.y - y.y; d.z = x.z - y.z; d.w = x.w - y.w;
        reinterpret_cast<float4*>(g_diff)[i] = d;
    }
}

// ---------------------------------------------------------------------------
// hpass: horizontal convs (E, h) + box via prefix. Row-pair packed f32x2.
// Block = 128 threads = 2 row-pairs (4 rows). Thread: 8 consecutive cols x row-pair.
// Shared layout bit-rotated: slot(x) = (x&7)*SST + (x>>3)  -> conflict-free
// sliding loads (lanes at fixed d access consecutive slots).
// ---------------------------------------------------------------------------
template<int K>
__global__ void __launch_bounds__(128, 4) hpass_t(int s) {
    constexpr int P = K / 2;
    constexpr int XW = WW + 2 * P;
    constexpr int SST = (XW + 7) / 8 + 1;
    __shared__ u64 spad[2][8 * SST];
    __shared__ u64 sE[K], sH[K];
    int tid = threadIdx.x;
    for (int i = tid; i < K; i += 128) { sE[i] = g_E2[s][i]; sH[i] = g_H2[s][i]; }
    int r0 = blockIdx.x * 4;
    for (int idx = tid; idx < 2 * XW; idx += 128) {
        int pr = (idx >= XW) ? 1 : 0;
        int x = idx - pr * XW;
        int c = x - P;
        c = c < 0 ? -c : c;
        c = c >= WW ? 2 * WW - 2 - c : c;
        const float* ra = g_diff + (size_t)(r0 + 2 * pr) * WW + c;
        spad[pr][(x & 7) * SST + (x >> 3)] = pk2(ra[0], ra[WW]);
    }
    __syncthreads();

    int tx = tid & 63;
    const u64* sp = spad[tid >> 6];
    u64 w[8], AE[8], AH[8];
    float2 Sa[8];
    float Px = 0.f, Py = 0.f;
#pragma unroll
    for (int i = 0; i < 8; i++) { AE[i] = 0ull; AH[i] = 0ull; }

    // preload tau = 0..7 (slots), prefix open checkpoints
#pragma unroll
    for (int t = 0; t < 8; ++t) {
        u64 v = sp[t * SST + tx];
        w[t] = v;
        Sa[t].x = -Px; Sa[t].y = -Py;
        float vx, vy; un2(v, vx, vy);
        Px += vx; Py += vy;
        if (t >= K - 1) { Sa[t - K + 1].x += Px; Sa[t - K + 1].y += Py; }  // K<=8 only
    }

    constexpr int MA = (K > 9) ? ((K - 9) / 8) * 8 : 0;
    for (int m = 0; m < MA / 8; ++m) {
#pragma unroll
        for (int jj = 0; jj < 8; ++jj) {
            int d = m * 8 + jj;
            u64 e2 = sE[d], h2 = sH[d];
#pragma unroll
            for (int rr = 0; rr < 8; ++rr) {
                u64 v = w[(jj + rr) & 7];
                AE[rr] = fma2(e2, v, AE[rr]);
                AH[rr] = fma2(h2, v, AH[rr]);
            }
            u64 nv = sp[jj * SST + tx + m + 1];   // x = j0+d+8 -> slot jj, col tx+m+1
            w[jj] = nv;
            float vx, vy; un2(nv, vx, vy);
            Px += vx; Py += vy;
        }
    }
#pragma unroll
    for (int e = 0; e < K - MA; ++e) {
        const int d = MA + e;
        u64 e2 = sE[d], h2 = sH[d];
#pragma unroll
        for (int rr = 0; rr < 8; ++rr) {
            u64 v = w[(d + rr) & 7];
            AE[rr] = fma2(e2, v, AE[rr]);
            AH[rr] = fma2(h2, v, AH[rr]);
        }
        if (d <= K - 2) {
            u64 nv = sp[(d & 7) * SST + tx + ((d + 8) >> 3)];
            w[d & 7] = nv;
            float vx, vy; un2(nv, vx, vy);
            Px += vx; Py += vy;
            if (d >= K - 9) { Sa[d + 9 - K].x += Px; Sa[d + 9 - K].y += Py; }
        }
    }

    // stores: U = E-conv, V = h-conv, S = box
    int j0 = tx * 8;
    size_t rbase = (size_t)(r0 + 2 * (tid >> 6)) * WW + j0;
    float la[8], lb[8];
#pragma unroll
    for (int rr = 0; rr < 8; ++rr) un2(AE[rr], la[rr], lb[rr]);
    *(float4*)(g_U + rbase)          = make_float4(la[0], la[1], la[2], la[3]);
    *(float4*)(g_U + rbase + 4)      = make_float4(la[4], la[5], la[6], la[7]);
    *(float4*)(g_U + rbase + WW)     = make_float4(lb[0], lb[1], lb[2], lb[3]);
    *(float4*)(g_U + rbase + WW + 4) = make_float4(lb[4], lb[5], lb[6], lb[7]);
#pragma unroll
    for (int rr = 0; rr < 8; ++rr) un2(AH[rr], la[rr], lb[rr]);
    *(float4*)(g_V + rbase)          = make_float4(la[0], la[1], la[2], la[3]);
    *(float4*)(g_V + rbase + 4)      = make_float4(la[4], la[5], la[6], la[7]);
    *(float4*)(g_V + rbase + WW)     = make_float4(lb[0], lb[1], lb[2], lb[3]);
    *(float4*)(g_V + rbase + WW + 4) = make_float4(lb[4], lb[5], lb[6], lb[7]);
#pragma unroll
    for (int rr = 0; rr < 8; ++rr) { la[rr] = Sa[rr].x; lb[rr] = Sa[rr].y; }
    *(float4*)(g_S + rbase)          = make_float4(la[0], la[1], la[2], la[3]);
    *(float4*)(g_S + rbase + 4)      = make_float4(la[4], la[5], la[6], la[7]);
    *(float4*)(g_S + rbase + WW)     = make_float4(lb[0], lb[1], lb[2], lb[3]);
    *(float4*)(g_S + rbase + WW + 4) = make_float4(lb[4], lb[5], lb[6], lb[7]);
}

// ---------------------------------------------------------------------------
// vpass: vertical convs A = h (x) U + E (x) V, minus cc * box(S), square, reduce.
// Column-pair packed f32x2, 16-row register tile, 16-deep sliding value window.
// ---------------------------------------------------------------------------
template<int K>
__global__ void __launch_bounds__(128, 3) vpass_t(int s) {
    constexpr int P = K / 2;
    __shared__ u64 sE[K], sH[K];
    __shared__ float sred[4];
    int tid = threadIdx.x;
    for (int i = tid; i < K; i += 128) { sE[i] = g_E2[s][i]; sH[i] = g_H2[s][i]; }
    __syncthreads();

    int col2 = blockIdx.x * 128 + tid;
    int i0 = blockIdx.y * 16;
    size_t ib = (size_t)blockIdx.z * (HH * W2C);
    const u64* __restrict__ Uq = (const u64*)g_U + ib;
    const u64* __restrict__ Vq = (const u64*)g_V + ib;
    const float2* __restrict__ Sq = (const float2*)g_S + ib;

    u64 wu[16], wv[16], A[16];
    float2 Sa[16];
    float Px = 0.f, Py = 0.f;
#pragma unroll
    for (int i = 0; i < 16; i++) A[i] = 0ull;
    int base = i0 - P;

#pragma unroll
    for (int t = 0; t < 16; ++t) {
        int r = base + t; r = r < 0 ? -r : r; r = r >= HH ? 2 * HH - 2 - r : r;
        int off = r * W2C + col2;
        wu[t] = Uq[off]; wv[t] = Vq[off];
        float2 sv = Sq[off];
        Sa[t].x = -Px; Sa[t].y = -Py;
        Px += sv.x; Py += sv.y;
        if (t >= K - 1) { Sa[t - K + 1].x += Px; Sa[t - K + 1].y += Py; }  // K<=16 only
    }

    constexpr int MA = (K > 17) ? ((K - 17) / 16) * 16 : 0;
    for (int m = 0; m < MA / 16; ++m) {
#pragma unroll
        for (int jj = 0; jj < 16; ++jj) {
            int d = m * 16 + jj;
            u64 e2 = sE[d], h2 = sH[d];
#pragma unroll
            for (int rr = 0; rr < 16; ++rr) {
                A[rr] = fma2(h2, wu[(jj + rr) & 15], A[rr]);
                A[rr] = fma2(e2, wv[(jj + rr) & 15], A[rr]);
            }
            int r = base + d + 16; r = r < 0 ? -r : r; r = r >= HH ? 2 * HH - 2 - r : r;
            int off = r * W2C + col2;
            wu[jj] = Uq[off]; wv[jj] = Vq[off];
            float2 sv = Sq[off];
            Px += sv.x; Py += sv.y;
        }
    }
#pragma unroll
    for (int e = 0; e < K - MA; ++e) {
        const int d = MA + e;
        u64 e2 = sE[d], h2 = sH[d];
#pragma unroll
        for (int rr = 0; rr < 16; ++rr) {
            A[rr] = fma2(h2, wu[(d + rr) & 15], A[rr]);
            A[rr] = fma2(e2, wv[(d + rr) & 15], A[rr]);
        }
        if (d <= K - 2) {
            int r = base + d + 16; r = r < 0 ? -r : r; r = r >= HH ? 2 * HH - 2 - r : r;
            int off = r * W2C + col2;
            wu[d & 15] = Uq[off]; wv[d & 15] = Vq[off];
            float2 sv = Sq[off];
            Px += sv.x; Py += sv.y;
            if (d >= K - 17) { Sa[d + 17 - K].x += Px; Sa[d + 17 - K].y += Py; }
        }
    }

    float cc = g_cc[s];
    float sq = 0.f;
#pragma unroll
    for (int rr = 0; rr < 16; ++rr) {
        float ax, ay; un2(A[rr], ax, ay);
        float vx = fmaf(-cc, Sa[rr].x, ax);
        float vy = fmaf(-cc, Sa[rr].y, ay);
        sq = fmaf(vx, vx, sq);
        sq = fmaf(vy, vy, sq);
    }
#pragma unroll
    for (int o = 16; o > 0; o >>= 1) sq += __shfl_xor_sync(0xffffffffu, sq, o);
    if ((tid & 31) == 0) sred[tid >> 5] = sq;
    __syncthreads();
    if (tid == 0)
        atomicAdd(&g_acc[s], (double)(sred[0] + sred[1] + sred[2] + sred[3]));
}

// ---------------------------------------------------------------------------
__global__ void fin_kernel(float* out) {
    double L = 0.0;
    for (int s = 0; s < NSIG; s++) L += (double)c_w[s] * g_acc[s];
    out[0] = (float)(L / (double)NPIX);
}

// ---------------------------------------------------------------------------
extern "C" void kernel_launch(void* const* d_in, const int* in_sizes, int n_in,
                              void* d_out, int out_size) {
    const float* input  = (const float*)d_in[0];
    const float* target = (const float*)d_in[1];

    init_kernel<<<NSIG, 160>>>();
    diff_kernel<<<(NPIX / 4 + 255) / 256, 256>>>(input, target);

    dim3 vg(2, HH / 16, NC);
    hpass_t<5>  <<<1536, 128>>>(0);  vpass_t<5>  <<<vg, 128>>>(0);
    hpass_t<11> <<<1536, 128>>>(1);  vpass_t<11> <<<vg, 128>>>(1);
    hpass_t<21> <<<1536, 128>>>(2);  vpass_t<21> <<<vg, 128>>>(2);
    hpass_t<39> <<<1536, 128>>>(3);  vpass_t<39> <<<vg, 128>>>(3);
    hpass_t<77> <<<1536, 128>>>(4);  vpass_t<77> <<<vg, 128>>>(4);
    hpass_t<155><<<1536, 128>>>(5);  vpass_t<155><<<vg, 128>>>(5);
    fin_kernel<<<1, 1>>>((float*)d_out);
}

// round 6
// speedup vs baseline: 1.9919x; 1.0595x over previous
#include <cuda_runtime.h>
#include <math.h>

#define HH 512
#define WW 512
#define W2C 256
#define NC 12
#define NPIX (NC*HH*WW)
#define NSIG 6
#define MAXK 155
#define DPI 3.14159265358979323846

typedef unsigned long long u64;

__device__ float g_diff[NPIX];
__device__ float g_U[NSIG][NPIX];
__device__ float g_V[NSIG][NPIX];
__device__ float g_S[NSIG][NPIX];
__device__ u64   g_E2[NSIG][MAXK];
__device__ u64   g_H2[NSIG][MAXK];
__device__ float g_cc[NSIG];
__device__ double g_acc[NSIG];

__constant__ int    c_k[NSIG]   = {5, 11, 21, 39, 77, 155};
__constant__ double c_sig[NSIG] = {0.6, 1.2, 2.4, 4.8, 9.6, 19.2};
__constant__ float  c_w[NSIG]   = {600.f, 500.f, 400.f, 20.f, 10.f, 10.f};

__device__ __forceinline__ u64 pk2(float lo, float hi) {
    u64 r; asm("mov.b64 %0,{%1,%2};" : "=l"(r) : "f"(lo), "f"(hi)); return r;
}
__device__ __forceinline__ void un2(u64 v, float& lo, float& hi) {
    asm("mov.b64 {%0,%1},%2;" : "=f"(lo), "=f"(hi) : "l"(v));
}
__device__ __forceinline__ u64 fma2(u64 a, u64 b, u64 c) {
    u64 d; asm("fma.rn.f32x2 %0,%1,%2,%3;" : "=l"(d) : "l"(a), "l"(b), "l"(c)); return d;
}

// ---------------------------------------------------------------------------
__global__ void init_kernel() {
    int s = blockIdx.x;
    int k = c_k[s];
    double ss = c_sig[s] * c_sig[s];
    int t = threadIdx.x;
    if (t == 0) g_acc[s] = 0.0;
    if (t < k) {
        double x = (double)t - (double)(k - 1) * 0.5;
        double e = exp(-(x * x) / (2.0 * ss));
        double h = (x * x - ss) * e / (2.0 * DPI * ss * ss);
        g_E2[s][t] = pk2((float)e, (float)e);
        g_H2[s][t] = pk2((float)h, (float)h);
    }
    __syncthreads();
    if (t == 0) {
        double sg = 0.0, sh = 0.0;
        for (int i = 0; i < k; i++) {
            float e, e1, h, h1;
            un2(g_E2[s][i], e, e1);
            un2(g_H2[s][i], h, h1);
            sg += (double)e; sh += (double)h;
        }
        g_cc[s] = (float)(2.0 * sg * sh / ((double)k * (double)k));
    }
}

// ---------------------------------------------------------------------------
__global__ void diff_kernel(const float* __restrict__ a, const float* __restrict__ b) {
    int i = blockIdx.x * blockDim.x + threadIdx.x;
    if (i < NPIX / 4) {
        float4 x = reinterpret_cast<const float4*>(a)[i];
        float4 y = reinterpret_cast<const float4*>(b)[i];
        float4 d;
        d.x = x.x - y.x; d.y = x.y - y.y; d.z = x.z - y.z; d.w = x.w - y.w;
        reinterpret_cast<float4*>(g_diff)[i] = d;
    }
}

// ---------------------------------------------------------------------------
// hpass body: horizontal convs (E, h) + box via prefix. Row-pair packed f32x2.
// Writes into per-sigma U/V/S buffers.
// ---------------------------------------------------------------------------
template<int K>
__device__ __forceinline__ void hpass_body(int s, int bx, u64* smbuf) {
    constexpr int P = K / 2;
    constexpr int XW = WW + 2 * P;
    constexpr int SST = (XW + 7) / 8 + 1;
    u64* spad0 = smbuf;                 // [2][8*SST]
    u64* sE = smbuf + 2 * 8 * SST;      // [K]
    u64* sH = sE + K;                   // [K]
    int tid = threadIdx.x;
    for (int i = tid; i < K; i += 128) { sE[i] = g_E2[s][i]; sH[i] = g_H2[s][i]; }
    int r0 = bx * 4;
    for (int idx = tid; idx < 2 * XW; idx += 128) {
        int pr = (idx >= XW) ? 1 : 0;
        int x = idx - pr * XW;
        int c = x - P;
        c = c < 0 ? -c : c;
        c = c >= WW ? 2 * WW - 2 - c : c;
        const float* ra = g_diff + (size_t)(r0 + 2 * pr) * WW + c;
        spad0[pr * 8 * SST + (x & 7) * SST + (x >> 3)] = pk2(ra[0], ra[WW]);
    }
    __syncthreads();

    int tx = tid & 63;
    const u64* sp = spad0 + (tid >> 6) * 8 * SST;
    u64 w[8], AE[8], AH[8];
    float2 Sa[8];
    float Px = 0.f, Py = 0.f;
#pragma unroll
    for (int i = 0; i < 8; i++) { AE[i] = 0ull; AH[i] = 0ull; }

#pragma unroll
    for (int t = 0; t < 8; ++t) {
        u64 v = sp[t * SST + tx];
        w[t] = v;
        Sa[t].x = -Px; Sa[t].y = -Py;
        float vx, vy; un2(v, vx, vy);
        Px += vx; Py += vy;
        if (t >= K - 1) { Sa[t - K + 1].x += Px; Sa[t - K + 1].y += Py; }
    }

    constexpr int MA = (K > 9) ? ((K - 9) / 8) * 8 : 0;
    for (int m = 0; m < MA / 8; ++m) {
#pragma unroll
        for (int jj = 0; jj < 8; ++jj) {
            int d = m * 8 + jj;
            u64 e2 = sE[d], h2 = sH[d];
#pragma unroll
            for (int rr = 0; rr < 8; ++rr) {
                u64 v = w[(jj + rr) & 7];
                AE[rr] = fma2(e2, v, AE[rr]);
                AH[rr] = fma2(h2, v, AH[rr]);
            }
            u64 nv = sp[jj * SST + tx + m + 1];
            w[jj] = nv;
            float vx, vy; un2(nv, vx, vy);
            Px += vx; Py += vy;
        }
    }
#pragma unroll
    for (int e = 0; e < K - MA; ++e) {
        const int d = MA + e;
        u64 e2 = sE[d], h2 = sH[d];
#pragma unroll
        for (int rr = 0; rr < 8; ++rr) {
            u64 v = w[(d + rr) & 7];
            AE[rr] = fma2(e2, v, AE[rr]);
            AH[rr] = fma2(h2, v, AH[rr]);
        }
        if (d <= K - 2) {
            u64 nv = sp[(d & 7) * SST + tx + ((d + 8) >> 3)];
            w[d & 7] = nv;
            float vx, vy; un2(nv, vx, vy);
            Px += vx; Py += vy;
            if (d >= K - 9) { Sa[d + 9 - K].x += Px; Sa[d + 9 - K].y += Py; }
        }
    }

    float* Ub = g_U[s];
    float* Vb = g_V[s];
    float* Sb = g_S[s];
    int j0 = tx * 8;
    size_t rbase = (size_t)(r0 + 2 * (tid >> 6)) * WW + j0;
    float la[8], lb[8];
#pragma unroll
    for (int rr = 0; rr < 8; ++rr) un2(AE[rr], la[rr], lb[rr]);
    *(float4*)(Ub + rbase)          = make_float4(la[0], la[1], la[2], la[3]);
    *(float4*)(Ub + rbase + 4)      = make_float4(la[4], la[5], la[6], la[7]);
    *(float4*)(Ub + rbase + WW)     = make_float4(lb[0], lb[1], lb[2], lb[3]);
    *(float4*)(Ub + rbase + WW + 4) = make_float4(lb[4], lb[5], lb[6], lb[7]);
#pragma unroll
    for (int rr = 0; rr < 8; ++rr) un2(AH[rr], la[rr], lb[rr]);
    *(float4*)(Vb + rbase)          = make_float4(la[0], la[1], la[2], la[3]);
    *(float4*)(Vb + rbase + 4)      = make_float4(la[4], la[5], la[6], la[7]);
    *(float4*)(Vb + rbase + WW)     = make_float4(lb[0], lb[1], lb[2], lb[3]);
    *(float4*)(Vb + rbase + WW + 4) = make_float4(lb[4], lb[5], lb[6], lb[7]);
#pragma unroll
    for (int rr = 0; rr < 8; ++rr) { la[rr] = Sa[rr].x; lb[rr] = Sa[rr].y; }
    *(float4*)(Sb + rbase)          = make_float4(la[0], la[1], la[2], la[3]);
    *(float4*)(Sb + rbase + 4)      = make_float4(la[4], la[5], la[6], la[7]);
    *(float4*)(Sb + rbase + WW)     = make_float4(lb[0], lb[1], lb[2], lb[3]);
    *(float4*)(Sb + rbase + WW + 4) = make_float4(lb[4], lb[5], lb[6], lb[7]);
}

// Fat hpass: all sigmas in one launch, descending K for load balance.
__global__ void __launch_bounds__(128, 4) hpass_all() {
    __shared__ alignas(16) u64 smbuf[1672];
    int b = blockIdx.x;
    int s = b / 1536;           // 0..5 in launch order
    int bx = b - s * 1536;
    switch (s) {
        case 0: hpass_body<155>(5, bx, smbuf); break;
        case 1: hpass_body<77> (4, bx, smbuf); break;
        case 2: hpass_body<39> (3, bx, smbuf); break;
        case 3: hpass_body<21> (2, bx, smbuf); break;
        case 4: hpass_body<11> (1, bx, smbuf); break;
        default:hpass_body<5>  (0, bx, smbuf); break;
    }
}

// ---------------------------------------------------------------------------
// vpass body: vertical convs A = h (x) U + E (x) V, minus cc * box(S), square, reduce.
// Reads per-sigma U/V/S buffers.
// ---------------------------------------------------------------------------
template<int K>
__device__ __forceinline__ void vpass_body(int s, int bx, int by, int bz, u64* smbuf) {
    constexpr int P = K / 2;
    u64* sE = smbuf;            // [K]
    u64* sH = sE + K;           // [K]
    float* sred = (float*)(sH + K);
    int tid = threadIdx.x;
    for (int i = tid; i < K; i += 128) { sE[i] = g_E2[s][i]; sH[i] = g_H2[s][i]; }
    __syncthreads();

    int col2 = bx * 128 + tid;
    int i0 = by * 16;
    size_t ib = (size_t)bz * (HH * W2C);
    const u64* __restrict__ Uq = (const u64*)g_U[s] + ib;
    const u64* __restrict__ Vq = (const u64*)g_V[s] + ib;
    const float2* __restrict__ Sq = (const float2*)g_S[s] + ib;

    u64 wu[16], wv[16], A[16];
    float2 Sa[16];
    float Px = 0.f, Py = 0.f;
#pragma unroll
    for (int i = 0; i < 16; i++) A[i] = 0ull;
    int base = i0 - P;

#pragma unroll
    for (int t = 0; t < 16; ++t) {
        int r = base + t; r = r < 0 ? -r : r; r = r >= HH ? 2 * HH - 2 - r : r;
        int off = r * W2C + col2;
        wu[t] = Uq[off]; wv[t] = Vq[off];
        float2 sv = Sq[off];
        Sa[t].x = -Px; Sa[t].y = -Py;
        Px += sv.x; Py += sv.y;
        if (t >= K - 1) { Sa[t - K + 1].x += Px; Sa[t - K + 1].y += Py; }
    }

    constexpr int MA = (K > 17) ? ((K - 17) / 16) * 16 : 0;
    for (int m = 0; m < MA / 16; ++m) {
#pragma unroll
        for (int jj = 0; jj < 16; ++jj) {
            int d = m * 16 + jj;
            u64 e2 = sE[d], h2 = sH[d];
#pragma unroll
            for (int rr = 0; rr < 16; ++rr) {
                A[rr] = fma2(h2, wu[(jj + rr) & 15], A[rr]);
                A[rr] = fma2(e2, wv[(jj + rr) & 15], A[rr]);
            }
            int r = base + d + 16; r = r < 0 ? -r : r; r = r >= HH ? 2 * HH - 2 - r : r;
            int off = r * W2C + col2;
            wu[jj] = Uq[off]; wv[jj] = Vq[off];
            float2 sv = Sq[off];
            Px += sv.x; Py += sv.y;
        }
    }
#pragma unroll
    for (int e = 0; e < K - MA; ++e) {
        const int d = MA + e;
        u64 e2 = sE[d], h2 = sH[d];
#pragma unroll
        for (int rr = 0; rr < 16; ++rr) {
            A[rr] = fma2(h2, wu[(d + rr) & 15], A[rr]);
            A[rr] = fma2(e2, wv[(d + rr) & 15], A[rr]);
        }
        if (d <= K - 2) {
            int r = base + d + 16; r = r < 0 ? -r : r; r = r >= HH ? 2 * HH - 2 - r : r;
            int off = r * W2C + col2;
            wu[d & 15] = Uq[off]; wv[d & 15] = Vq[off];
            float2 sv = Sq[off];
            Px += sv.x; Py += sv.y;
            if (d >= K - 17) { Sa[d + 17 - K].x += Px; Sa[d + 17 - K].y += Py; }
        }
    }

    float cc = g_cc[s];
    float sq = 0.f;
#pragma unroll
    for (int rr = 0; rr < 16; ++rr) {
        float ax, ay; un2(A[rr], ax, ay);
        float vx = fmaf(-cc, Sa[rr].x, ax);
        float vy = fmaf(-cc, Sa[rr].y, ay);
        sq = fmaf(vx, vx, sq);
        sq = fmaf(vy, vy, sq);
    }
#pragma unroll
    for (int o = 16; o > 0; o >>= 1) sq += __shfl_xor_sync(0xffffffffu, sq, o);
    if ((tid & 31) == 0) sred[tid >> 5] = sq;
    __syncthreads();
    if (tid == 0)
        atomicAdd(&g_acc[s], (double)(sred[0] + sred[1] + sred[2] + sred[3]));
}

// Fat vpass: all sigmas, descending K; per sigma 768 blocks = (2, 32, 12).
__global__ void __launch_bounds__(128, 3) vpass_all() {
    __shared__ alignas(16) u64 smbuf[2 * MAXK + 4];
    int b = blockIdx.x;
    int s = b / 768;
    int id = b - s * 768;
    int bx = id & 1;
    int by = (id >> 1) & 31;
    int bz = id >> 6;
    switch (s) {
        case 0: vpass_body<155>(5, bx, by, bz, smbuf); break;
        case 1: vpass_body<77> (4, bx, by, bz, smbuf); break;
        case 2: vpass_body<39> (3, bx, by, bz, smbuf); break;
        case 3: vpass_body<21> (2, bx, by, bz, smbuf); break;
        case 4: vpass_body<11> (1, bx, by, bz, smbuf); break;
        default:vpass_body<5>  (0, bx, by, bz, smbuf); break;
    }
}

// ---------------------------------------------------------------------------
__global__ void fin_kernel(float* out) {
    double L = 0.0;
    for (int s = 0; s < NSIG; s++) L += (double)c_w[s] * g_acc[s];
    out[0] = (float)(L / (double)NPIX);
}

// ---------------------------------------------------------------------------
extern "C" void kernel_launch(void* const* d_in, const int* in_sizes, int n_in,
                              void* d_out, int out_size) {
    const float* input  = (const float*)d_in[0];
    const float* target = (const float*)d_in[1];

    init_kernel<<<NSIG, 160>>>();
    diff_kernel<<<(NPIX / 4 + 255) / 256, 256>>>(input, target);
    hpass_all<<<NSIG * 1536, 128>>>();
    vpass_all<<<NSIG * 768, 128>>>();
    fin_kernel<<<1, 1>>>((float*)d_out);
}